// round 10
// baseline (speedup 1.0000x reference)
#include <cuda_runtime.h>
#include <cuda_bf16.h>
#include <cstdint>
#include <math.h>

#define N_DATA 100000
#define NP     100352              // 1568 * 64
#define TILE   64
#define N_TILES (NP / TILE)        // 1568
#define NSPLIT 8
#define TPS    (N_TILES / NSPLIT)  // 196 tiles per split
#define SPLIT_PTS (TPS * TILE)     // 12544
#define D      64
#define BQ     2048
#define QBK    64                  // queries per screening CTA (M)
#define KNN    20
#define NCAND  24                  // survivors per (query, split)
#define TCAND  (NSPLIT * NCAND)    // 192

__device__ __nv_bfloat16 g_bh[NP * D];  // hi bf16, point-major rows (128B)
__device__ __nv_bfloat16 g_bl[NP * D];  // lo residual
__device__ float g_pp[NP];              // exact ||p||^2 (1e30 pad)
__device__ int   g_candI[BQ * TCAND];

// smem byte offsets (scr_k). Q/B rows padded to 144B for conflict-free LDSM.
#define OFF_QH   0                 // 64 x 144B = 9216
#define OFF_QL   9216
#define OFF_B    18432             // [buf]{hi 9216 | lo 9216} : buf*18432
#define OFF_DIST 55296             // 64 x 68 floats = 17408
#define OFF_PP   72704             // 2 x 64 floats
#define OFF_QQ   73216             // 64 floats
#define SCR_SMEM 73472
// epilogue lists alias the Q/B region
#define OFF_LD   0                 // 256*NCAND floats = 24576
#define OFF_LI   24576             // 256*NCAND ints

// ---------------------------------------------------------------------------
__device__ __forceinline__ void cp_async16(unsigned s, const void* gmem) {
    asm volatile("cp.async.cg.shared.global [%0], [%1], 16;" :: "r"(s), "l"(gmem));
}
#define CP_COMMIT() asm volatile("cp.async.commit_group;")
#define CP_WAIT1()  asm volatile("cp.async.wait_group 1;")
#define CP_WAIT0()  asm volatile("cp.async.wait_group 0;")

__device__ __forceinline__ unsigned smem_u32(const void* p) {
    unsigned a;
    asm("{ .reg .u64 t; cvta.to.shared.u64 t, %1; cvt.u32.u64 %0, t; }"
        : "=r"(a) : "l"(p));
    return a;
}

#define LDSM_X4(r, a) \
    asm volatile("ldmatrix.sync.aligned.m8n8.x4.shared.b16 {%0,%1,%2,%3}, [%4];" \
        : "=r"((r)[0]), "=r"((r)[1]), "=r"((r)[2]), "=r"((r)[3]) : "r"(a))
#define LDSM_X2(r0, r1, a) \
    asm volatile("ldmatrix.sync.aligned.m8n8.x2.shared.b16 {%0,%1}, [%2];" \
        : "=r"(r0), "=r"(r1) : "r"(a))

__device__ __forceinline__ void mma_bf16(float* c, const unsigned* a,
                                         unsigned b0, unsigned b1) {
    asm volatile(
        "mma.sync.aligned.m16n8k16.row.col.f32.bf16.bf16.f32 "
        "{%0,%1,%2,%3}, {%4,%5,%6,%7}, {%8,%9}, {%0,%1,%2,%3};"
        : "+f"(c[0]), "+f"(c[1]), "+f"(c[2]), "+f"(c[3])
        : "r"(a[0]), "r"(a[1]), "r"(a[2]), "r"(a[3]), "r"(b0), "r"(b1));
}

__device__ __forceinline__ void insC(float d, int idx, float* best, int* bestI,
                                     float& kth) {
    if (d < kth) {
#pragma unroll
        for (int k = 0; k < NCAND; k++) {
            if (d < best[k]) {
                float td = best[k]; best[k] = d; d = td;
                int ti = bestI[k]; bestI[k] = idx; idx = ti;
            }
        }
        kth = best[NCAND - 1];
    }
}

// ---------------------------------------------------------------------------
// Prep: bf16 hi/lo split of data (row-major, 128B rows) + exact ||p||^2
// ---------------------------------------------------------------------------
__global__ void prep_k(const float* __restrict__ data) {
    int p = blockIdx.x * 256 + threadIdx.x;
    if (p >= NP) return;
    bool v = p < N_DATA;
    float pp = 0.f;
#pragma unroll
    for (int c8 = 0; c8 < 8; c8++) {
        unsigned hi4[4], lo4[4];
#pragma unroll
        for (int i = 0; i < 4; i++) {
            float x0 = v ? data[p * D + c8 * 8 + i * 2 + 0] : 0.f;
            float x1 = v ? data[p * D + c8 * 8 + i * 2 + 1] : 0.f;
            pp += x0 * x0 + x1 * x1;
            __nv_bfloat16 h0 = __float2bfloat16_rn(x0);
            __nv_bfloat16 h1 = __float2bfloat16_rn(x1);
            __nv_bfloat16 l0 = __float2bfloat16_rn(x0 - __bfloat162float(h0));
            __nv_bfloat16 l1 = __float2bfloat16_rn(x1 - __bfloat162float(h1));
            hi4[i] = (unsigned)__bfloat16_as_ushort(h0)
                   | ((unsigned)__bfloat16_as_ushort(h1) << 16);
            lo4[i] = (unsigned)__bfloat16_as_ushort(l0)
                   | ((unsigned)__bfloat16_as_ushort(l1) << 16);
        }
        *reinterpret_cast<uint4*>(&g_bh[p * D + c8 * 8]) =
            make_uint4(hi4[0], hi4[1], hi4[2], hi4[3]);
        *reinterpret_cast<uint4*>(&g_bl[p * D + c8 * 8]) =
            make_uint4(lo4[0], lo4[1], lo4[2], lo4[3]);
    }
    g_pp[p] = v ? pp : 1e30f;
}

// ---------------------------------------------------------------------------
// MLP: x_dot = relu([x,t] @ W1 + b1) @ W2 + b2 ; write into out[:, 0:64]
// ---------------------------------------------------------------------------
__global__ __launch_bounds__(256) void mlp_k(
    const float* __restrict__ t, const float* __restrict__ z,
    const float* __restrict__ W1, const float* __restrict__ b1,
    const float* __restrict__ W2, const float* __restrict__ b2,
    float* __restrict__ out)
{
    __shared__ float sIn[16 * 68];
    __shared__ float sH[16 * 258];
    int tid = threadIdx.x;
    int r0 = blockIdx.x * 16;
    float tv = t[0];
    for (int i = tid; i < 16 * 65; i += 256) {
        int r = i / 65, c = i % 65;
        sIn[r * 68 + c] = (c < 64) ? z[(r0 + r) * 66 + c] : tv;
    }
    __syncthreads();
    {
        int r = tid & 15, jb = tid >> 4;
#pragma unroll
        for (int jj = 0; jj < 16; jj++) {
            int j = jb + jj * 16;
            float acc = b1[j];
#pragma unroll
            for (int i = 0; i < 65; i++) acc += sIn[r * 68 + i] * W1[i * 256 + j];
            sH[r * 258 + j] = fmaxf(acc, 0.f);
        }
    }
    __syncthreads();
    {
        int r = tid >> 4, db = tid & 15;
        int d0 = db * 4;
        float a0 = b2[d0], a1 = b2[d0 + 1], a2 = b2[d0 + 2], a3 = b2[d0 + 3];
#pragma unroll 8
        for (int j = 0; j < 256; j++) {
            float hv = sH[r * 258 + j];
            float4 w = *reinterpret_cast<const float4*>(W2 + j * 64 + d0);
            a0 += hv * w.x; a1 += hv * w.y; a2 += hv * w.z; a3 += hv * w.w;
        }
        int gq = r0 + r;
        out[gq * 66 + d0 + 0] = a0;
        out[gq * 66 + d0 + 1] = a1;
        out[gq * 66 + d0 + 2] = a2;
        out[gq * 66 + d0 + 3] = a3;
    }
}

// ---------------------------------------------------------------------------
// Screening: bf16 2-split mma.m16n8k16 (hh + lh + hl), 64q x 64p tiles.
// 8 warps: warp = (mstripe = wid>>1 [m16], nhalf = wid&1 [n32]).
// A fragments (queries) hoisted; B via ldmatrix from 144B-pitch smem.
// ---------------------------------------------------------------------------
__device__ __forceinline__ void loadB(unsigned smb, int tile, int buf, int tid) {
    const char* srcH = (const char*)g_bh + (size_t)tile * 8192;
    const char* srcL = (const char*)g_bl + (size_t)tile * 8192;
    unsigned dst = smb + OFF_B + buf * 18432;
#pragma unroll
    for (int i = 0; i < 2; i++) {
        int c = tid + i * 256;
        int r = c >> 3, ch = c & 7;
        cp_async16(dst + r * 144 + ch * 16, srcH + r * 128 + ch * 16);
        cp_async16(dst + 9216 + r * 144 + ch * 16, srcL + r * 128 + ch * 16);
    }
    if (tid < 16)
        cp_async16(smb + OFF_PP + buf * 256 + tid * 16,
                   (const char*)g_pp + (size_t)tile * 256 + tid * 16);
}

__global__ __launch_bounds__(256, 2) void scr_k(const float* __restrict__ z)
{
    extern __shared__ char sm[];
    unsigned smb = smem_u32(sm);
    int tid = threadIdx.x, lane = tid & 31, wid = tid >> 5;
    int q0 = blockIdx.x * QBK;
    int split = blockIdx.y;
    int tb = split * TPS;

    loadB(smb, tb + 0, 0, tid); CP_COMMIT();
    loadB(smb, tb + 1, 1, tid); CP_COMMIT();

    // stage queries hi/lo into 144B-pitch smem
#pragma unroll
    for (int i = 0; i < 2; i++) {
        int task = tid + i * 256;          // 512 = 64 rows x 8 chunks
        int r = task >> 3, c8 = task & 7;
        unsigned hi4[4], lo4[4];
#pragma unroll
        for (int j = 0; j < 4; j++) {
            float x0 = z[(q0 + r) * 66 + c8 * 8 + j * 2 + 0];
            float x1 = z[(q0 + r) * 66 + c8 * 8 + j * 2 + 1];
            __nv_bfloat16 h0 = __float2bfloat16_rn(x0);
            __nv_bfloat16 h1 = __float2bfloat16_rn(x1);
            __nv_bfloat16 l0 = __float2bfloat16_rn(x0 - __bfloat162float(h0));
            __nv_bfloat16 l1 = __float2bfloat16_rn(x1 - __bfloat162float(h1));
            hi4[j] = (unsigned)__bfloat16_as_ushort(h0)
                   | ((unsigned)__bfloat16_as_ushort(h1) << 16);
            lo4[j] = (unsigned)__bfloat16_as_ushort(l0)
                   | ((unsigned)__bfloat16_as_ushort(l1) << 16);
        }
        *reinterpret_cast<uint4*>(sm + OFF_QH + r * 144 + c8 * 16) =
            make_uint4(hi4[0], hi4[1], hi4[2], hi4[3]);
        *reinterpret_cast<uint4*>(sm + OFF_QL + r * 144 + c8 * 16) =
            make_uint4(lo4[0], lo4[1], lo4[2], lo4[3]);
    }
    if (tid < QBK) {
        float s = 0.f;
#pragma unroll 8
        for (int k = 0; k < D; k++) { float x = z[(q0 + tid) * 66 + k]; s += x * x; }
        *reinterpret_cast<float*>(sm + OFF_QQ + tid * 4) = s;
    }
    __syncthreads();

    int mstripe = wid >> 1, nhalf = wid & 1;

    // hoist A-hi fragments (4 k-steps x 4 regs); A-lo reloaded per tile k-step
    unsigned aOff = (mstripe * 16 + (lane & 15)) * 144 + ((lane >> 4) & 1) * 16;
    unsigned ah[4][4];
#pragma unroll
    for (int ks = 0; ks < 4; ks++)
        LDSM_X4(ah[ks], smb + OFF_QH + aOff + ks * 32);

    unsigned bOff = (nhalf * 32 + (lane & 7)) * 144 + ((lane >> 3) & 1) * 16;

    int r0q = mstripe * 16 + (lane >> 2), r1q = r0q + 8;
    float qq0 = *reinterpret_cast<float*>(sm + OFF_QQ + r0q * 4);
    float qq1 = *reinterpret_cast<float*>(sm + OFF_QQ + r1q * 4);

    float best[NCAND]; int bestI[NCAND]; float kth = 3.4e38f;
#pragma unroll
    for (int k = 0; k < NCAND; k++) { best[k] = 3.4e38f; bestI[k] = 0; }

    int sq_q = tid >> 2, sgrp = tid & 3;   // scan: 1 query x 16 points

    for (int t = 0; t < TPS; t++) {
        int cur = t & 1;
        if (t + 1 < TPS) CP_WAIT1(); else CP_WAIT0();
        __syncthreads();                   // B(t) ready; Dist(t-1) consumed

        float acc[4][4];
#pragma unroll
        for (int nt = 0; nt < 4; nt++)
#pragma unroll
            for (int i = 0; i < 4; i++) acc[nt][i] = 0.f;

        unsigned bBase = smb + OFF_B + cur * 18432;
#pragma unroll
        for (int ks = 0; ks < 4; ks++) {
            unsigned al[4];
            LDSM_X4(al, smb + OFF_QL + aOff + ks * 32);
#pragma unroll
            for (int nt = 0; nt < 4; nt++) {
                unsigned bh0, bh1, bl0, bl1;
                LDSM_X2(bh0, bh1, bBase + nt * 8 * 144 + bOff + ks * 32);
                LDSM_X2(bl0, bl1, bBase + 9216 + nt * 8 * 144 + bOff + ks * 32);
                mma_bf16(acc[nt], ah[ks], bh0, bh1);
                mma_bf16(acc[nt], al,     bh0, bh1);
                mma_bf16(acc[nt], ah[ks], bl0, bl1);
            }
        }

        // sq = qq + pp - 2*dot -> Dist
        const float* pp = reinterpret_cast<const float*>(sm + OFF_PP + cur * 256);
        float* Dist = reinterpret_cast<float*>(sm + OFF_DIST);
#pragma unroll
        for (int nt = 0; nt < 4; nt++) {
            int c0 = nhalf * 32 + nt * 8 + (lane & 3) * 2;
            float pp0 = pp[c0], pp1 = pp[c0 + 1];
            *reinterpret_cast<float2*>(&Dist[r0q * 68 + c0]) =
                make_float2(qq0 + pp0 - 2.f * acc[nt][0],
                            qq0 + pp1 - 2.f * acc[nt][1]);
            *reinterpret_cast<float2*>(&Dist[r1q * 68 + c0]) =
                make_float2(qq1 + pp0 - 2.f * acc[nt][2],
                            qq1 + pp1 - 2.f * acc[nt][3]);
        }
        __syncthreads();                   // Dist complete; B(cur) consumed

        if (t + 2 < TPS) { loadB(smb, tb + t + 2, cur, tid); CP_COMMIT(); }

        // scan Dist, guarded insert
        const float* Dist2 = reinterpret_cast<const float*>(sm + OFF_DIST);
        int pb = split * SPLIT_PTS + t * TILE + sgrp * 16;
#pragma unroll
        for (int c4 = 0; c4 < 4; c4++) {
            float4 v = *reinterpret_cast<const float4*>(
                &Dist2[sq_q * 68 + sgrp * 16 + c4 * 4]);
            insC(v.x, pb + c4 * 4 + 0, best, bestI, kth);
            insC(v.y, pb + c4 * 4 + 1, best, bestI, kth);
            insC(v.z, pb + c4 * 4 + 2, best, bestI, kth);
            insC(v.w, pb + c4 * 4 + 3, best, bestI, kth);
        }
    }
    __syncthreads();

    // dump lists (alias Q/B smem), merge 4 per query -> per-split top-24
    float* listD = reinterpret_cast<float*>(sm + OFF_LD);
    int*   listI = reinterpret_cast<int*>(sm + OFF_LI);
#pragma unroll
    for (int k = 0; k < NCAND; k++) {
        listD[tid * NCAND + k] = best[k];
        listI[tid * NCAND + k] = bestI[k];
    }
    __syncthreads();
    if (tid < QBK) {
        int ptr[4] = {0, 0, 0, 0};
        int gbase = (q0 + tid) * TCAND + split * NCAND;
        for (int o = 0; o < NCAND; o++) {
            float bd = 3.5e38f; int bl = 0;
#pragma unroll
            for (int l = 0; l < 4; l++) {
                if (ptr[l] < NCAND) {
                    float v = listD[(tid * 4 + l) * NCAND + ptr[l]];
                    if (v < bd) { bd = v; bl = l; }
                }
            }
            g_candI[gbase + o] = listI[(tid * 4 + bl) * NCAND + ptr[bl]];
            ptr[bl]++;
        }
    }
}

// ---------------------------------------------------------------------------
// Final: exact fp32 refine of TCAND candidates/query, top-20, weights, metrics.
// One warp per query, 8 queries per CTA.
// ---------------------------------------------------------------------------
__global__ __launch_bounds__(256) void fin2_k(
    const float* __restrict__ z, const float* __restrict__ data,
    const float* __restrict__ velocity, float* __restrict__ out)
{
    __shared__ float sQ[8][64];
    __shared__ float sqq[8];
    __shared__ float sCD[8][TCAND];
    __shared__ int   sCI[8][TCAND];
    __shared__ float selW[8][KNN];
    __shared__ int   selI[8][KNN];
    int tid = threadIdx.x, w = tid >> 5, l = tid & 31;
    int qi = blockIdx.x * 8 + w;

    float part = 0.f;
    for (int k = l; k < 64; k += 32) {
        float x = z[qi * 66 + k];
        sQ[w][k] = x; part += x * x;
    }
#pragma unroll
    for (int o = 16; o; o >>= 1) part += __shfl_xor_sync(0xffffffffu, part, o);
    if (l == 0) sqq[w] = part;
    __syncwarp();
    float qq = sqq[w];

#pragma unroll
    for (int j = 0; j < TCAND / 32; j++) {
        int c = l * (TCAND / 32) + j;
        int idx = g_candI[qi * TCAND + c];
        float dt = 0.f, pp = 0.f;
#pragma unroll
        for (int k4 = 0; k4 < 16; k4++) {
            float4 p = *reinterpret_cast<const float4*>(&data[idx * 64 + k4 * 4]);
            pp += p.x * p.x + p.y * p.y + p.z * p.z + p.w * p.w;
            dt += sQ[w][k4 * 4 + 0] * p.x + sQ[w][k4 * 4 + 1] * p.y
                + sQ[w][k4 * 4 + 2] * p.z + sQ[w][k4 * 4 + 3] * p.w;
        }
        sCD[w][c] = qq + pp - 2.f * dt;
        sCI[w][c] = idx;
    }
    __syncwarp();

    if (l == 0) {
        float best[KNN]; int bi[KNN]; float kth = 3.4e38f;
#pragma unroll
        for (int k = 0; k < KNN; k++) { best[k] = 3.4e38f; bi[k] = 0; }
        for (int c = 0; c < TCAND; c++) {
            float d = sCD[w][c]; int idx = sCI[w][c];
            if (d < kth) {
#pragma unroll
                for (int k = 0; k < KNN; k++) {
                    if (d < best[k]) {
                        float td = best[k]; best[k] = d; d = td;
                        int ti = bi[k]; bi[k] = idx; idx = ti;
                    }
                }
                kth = best[KNN - 1];
            }
        }
        float d19 = sqrtf(fmaxf(best[KNN - 1], 1e-30f));
        float h = fmaxf(d19, 1e-12f);
        float inv2h2 = 1.f / (2.f * h * h);
        float ws = 0.f, wv[KNN];
#pragma unroll
        for (int o = 0; o < KNN; o++) {
            float d = sqrtf(fmaxf(best[o], 1e-30f));
            wv[o] = expf(-d * d * inv2h2);
            ws += wv[o];
        }
        float inv = 1.f / (ws + 1e-12f);
#pragma unroll
        for (int o = 0; o < KNN; o++) { selW[w][o] = wv[o] * inv; selI[w][o] = bi[o]; }
    }
    __syncwarp();

    int d0 = l * 2;
    float u0 = 0.f, u1 = 0.f;
#pragma unroll
    for (int o = 0; o < KNN; o++) {
        float wt = selW[w][o]; int idx = selI[w][o];
        float2 v = *reinterpret_cast<const float2*>(&velocity[idx * 64 + d0]);
        u0 += wt * v.x; u1 += wt * v.y;
    }
    float x0 = out[qi * 66 + d0], x1 = out[qi * 66 + d0 + 1];
    float pd = u0 * x0 + u1 * x1;
    float pu = u0 * u0 + u1 * u1;
    float px = x0 * x0 + x1 * x1;
#pragma unroll
    for (int o = 16; o; o >>= 1) {
        pd += __shfl_xor_sync(0xffffffffu, pd, o);
        pu += __shfl_xor_sync(0xffffffffu, pu, o);
        px += __shfl_xor_sync(0xffffffffu, px, o);
    }
    if (l == 0) {
        float nu = fmaxf(sqrtf(pu), 1e-8f);
        float nx = fmaxf(sqrtf(px), 1e-8f);
        out[qi * 66 + 64] = 1.f - pd / (nu * nx);
        out[qi * 66 + 65] = pu - 2.f * pd + px;
    }
}

// ---------------------------------------------------------------------------
extern "C" void kernel_launch(void* const* d_in, const int* in_sizes, int n_in,
                              void* d_out, int out_size)
{
    const float* t        = (const float*)d_in[0];
    const float* z        = (const float*)d_in[1];
    const float* data     = (const float*)d_in[2];
    const float* velocity = (const float*)d_in[3];
    const float* W1       = (const float*)d_in[4];
    const float* b1       = (const float*)d_in[5];
    const float* W2       = (const float*)d_in[6];
    const float* b2       = (const float*)d_in[7];
    float* out = (float*)d_out;

    cudaFuncSetAttribute(scr_k, cudaFuncAttributeMaxDynamicSharedMemorySize,
                         SCR_SMEM);

    prep_k<<<NP / 256, 256>>>(data);
    mlp_k<<<BQ / 16, 256>>>(t, z, W1, b1, W2, b2, out);
    scr_k<<<dim3(BQ / QBK, NSPLIT), 256, SCR_SMEM>>>(z);
    fin2_k<<<BQ / 8, 256>>>(z, data, velocity, out);
}